// round 14
// baseline (speedup 1.0000x reference)
#include <cuda_runtime.h>
#include <cuda_bf16.h>
#include <math.h>
#include <stdint.h>

#define D_MODEL 128
#define D_STATE 64
#define LSEQ    1024
#define BATCH   32

// Scratch (static device globals: allocation-free per harness rules)
__device__ float g_K  [D_MODEL * LSEQ];                  // REVERSED kernel Krev[d][s] = K[d][1023-s]
__device__ float g_act[BATCH * D_MODEL * LSEQ];          // post-GELU activations
__device__ uint32_t g_Wfh[16384];                        // W1 hi, mma-fragment order
__device__ uint32_t g_Wfl[16384];                        // W1 lo, mma-fragment order

// ---------------------------------------------------------------------------
// helpers
// ---------------------------------------------------------------------------
__device__ __forceinline__ uint16_t bfbits(float x) {
    __nv_bfloat16 h = __float2bfloat16(x);
    return *(uint16_t*)&h;
}
__device__ __forceinline__ float bf2f(uint16_t b) {
    __nv_bfloat16 h = *(__nv_bfloat16*)&b;
    return __bfloat162float(h);
}
__device__ __forceinline__ uint32_t packbf2(float a, float b) {
    uint16_t ha = bfbits(a), hb = bfbits(b);
    return (uint32_t)ha | ((uint32_t)hb << 16);
}
// mma.sync m16n8k16 row.col f32.bf16.bf16.f32 (sm_80+, no 'a' feature needed)
__device__ __forceinline__ void mma16816(float* c, const uint32_t* a, const uint32_t* b) {
    asm volatile(
        "mma.sync.aligned.m16n8k16.row.col.f32.bf16.bf16.f32 "
        "{%0,%1,%2,%3}, {%4,%5,%6,%7}, {%8,%9}, {%0,%1,%2,%3};"
        : "+f"(c[0]), "+f"(c[1]), "+f"(c[2]), "+f"(c[3])
        : "r"(a[0]), "r"(a[1]), "r"(a[2]), "r"(a[3]), "r"(b[0]), "r"(b[1]));
}

// fp32 Cody-Waite mod-2pi of an fp32 value (err <= ~7e-7 abs).
__device__ __forceinline__ float red2pi(float ph) {
    float n = rintf(ph * 0.15915494309189535f);
    float r = fmaf(n, -6.28125f, ph);
    return fmaf(n, -1.9353071795864769e-3f, r);
}

// ---------------------------------------------------------------------------
// Kernel A: K[d,m], stored REVERSED: g_K[d][1023-m] = K[d][m]
// ---------------------------------------------------------------------------
__global__ void k_genK(const float* __restrict__ log_dt,
                       const float* __restrict__ log_A_real,
                       const float* __restrict__ A_imag,
                       const float* __restrict__ B_re, const float* __restrict__ B_im,
                       const float* __restrict__ C_re, const float* __restrict__ C_im)
{
    const int d = blockIdx.x;
    __shared__ float arS[64], aiS[64], grS[64], giS[64];
    const int tid = threadIdx.x;

    if (tid < 64) {
        int n = tid;
        float dtv = expf(log_dt[d]);
        float Ar  = -expf(log_A_real[d * 64 + n]);
        float Ai  = A_imag[d * 64 + n];
        float ar  = Ar * dtv;
        float ai  = Ai * dtv;
        float r0  = red2pi(ai);
        float s, c;
        __sincosf(r0, &s, &c);
        float e   = expf(ar);
        float Abr = e * c, Abi = e * s;
        float nr = Abr - 1.0f, ni = Abi;
        float inv = 1.0f / (Ar * Ar + Ai * Ai);
        float br = (nr * Ar + ni * Ai) * inv;
        float bi = (ni * Ar - nr * Ai) * inv;
        float Br = B_re[d * 64 + n], Bi = B_im[d * 64 + n];
        float tr = br * Br - bi * Bi;
        float ti = br * Bi + bi * Br;
        float Cr = C_re[d * 64 + n], Ci = C_im[d * 64 + n];
        grS[n] = Cr * tr - Ci * ti;
        giS[n] = Cr * ti + Ci * tr;
        arS[n] = ar;
        aiS[n] = ai;
    }
    __syncthreads();

    const int l = blockIdx.y * 256 + tid;
    float lf = (float)l;
    float acc = 0.0f;
    #pragma unroll 4
    for (int n = 0; n < 64; n++) {
        float ph = aiS[n] * lf;
        float r  = red2pi(ph);
        float s, c;
        __sincosf(r, &s, &c);
        float e = __expf(arS[n] * lf);
        acc += e * (grS[n] * c - giS[n] * s);
    }
    g_K[d * LSEQ + (LSEQ - 1 - l)] = acc;      // reversed store
}

// ---------------------------------------------------------------------------
// W1 -> bf16 hi/lo in mma-fragment order (see k_head).
// ---------------------------------------------------------------------------
__global__ void k_prepW(const float* __restrict__ W1)
{
    int t = blockIdx.x * 256 + threadIdx.x;    // 0..4095
    int lane = t & 31;
    int ks = (t >> 5) & 7;
    int w  = (t >> 8) & 7;
    int h  = (t >> 11) & 1;
    int r  = lane >> 2;
    int cu = ks * 8 + (lane & 3);
    int oa0 = h * 128 + 16 * w + r, oa1 = oa0 + 8;
    int rowsel[4] = {oa0, oa1, oa0, oa1};
    int dsel[4]   = {2 * cu, 2 * cu, 2 * cu + 8, 2 * cu + 8};
    uint32_t hi[4], lo[4];
    #pragma unroll
    for (int i = 0; i < 4; i++) {
        float v0 = W1[rowsel[i] * 128 + dsel[i]];
        float v1 = W1[rowsel[i] * 128 + dsel[i] + 1];
        uint16_t h0 = bfbits(v0), h1 = bfbits(v1);
        uint16_t l0 = bfbits(v0 - bf2f(h0)), l1 = bfbits(v1 - bf2f(h1));
        hi[i] = (uint32_t)h0 | ((uint32_t)h1 << 16);
        lo[i] = (uint32_t)l0 | ((uint32_t)l1 << 16);
    }
    uint4 hv = {hi[0], hi[1], hi[2], hi[3]};
    uint4 lv = {lo[0], lo[1], lo[2], lo[3]};
    *(uint4*)&g_Wfh[(size_t)t * 4] = hv;
    *(uint4*)&g_Wfl[(size_t)t * 4] = lv;
}

// ---------------------------------------------------------------------------
// Kernel B: per-(d, batch-half) Toeplitz conv via mma.sync bf16 hi/lo.
// kk-OUTER / j-INNER restructure: B frags loaded once per kk (reused over
// avg 4.5 j), A frags = 2x LDS.64 per term-set from pair-packed A2 arrays
// (A2[i] = {A[i], A[i+8]}; a3==a0 makes A2[p-8] = {a2, a3}).
// All 8 j accumulators live in registers (NB=16 -> 64 acc regs).
// grid (128 d, 2 batch-halves), 2 CTAs/SM, one wave.
// ---------------------------------------------------------------------------
#define NB       16                       // batch rows per CTA
#define PKB      2064                     // ub row pitch bytes (1032 bf16)
#define OFF_A2H  0                        // 1152 uint2 = 9216 B
#define OFF_A2L  9216
#define OFF_STG  18432                    // max(K scratch 4096, 16*136*4=8704)
#define OFF_UBH  27136                    // NB * 2064 = 33024
#define OFF_UBL  60160
#define SMEM_CONV 93184

__global__ void __launch_bounds__(256, 2) k_conv(const float* __restrict__ u,
                                                 const float* __restrict__ Dvec)
{
    extern __shared__ __align__(16) char smem[];
    uint2* A2H = (uint2*)(smem + OFF_A2H);
    uint2* A2L = (uint2*)(smem + OFF_A2L);
    float* stg = (float*)(smem + OFF_STG);

    const int d    = blockIdx.x;
    const int bh   = blockIdx.y;          // batch half (0/1)
    const int tid  = threadIdx.x;
    const int w    = tid >> 5;
    const int lane = tid & 31;

    // ---- Krev fp32 into scratch ----
    for (int i = tid; i < 1024; i += 256) stg[i] = g_K[d * LSEQ + i];
    __syncthreads();

    // ---- build pair-packed A arrays over raw index i in [0,1152) ----
    // logical il = i-8. A[i] = pack(Krev[il-128], Krev[il-129]) (zero outside
    // [128,1151]); A2[i] = {A[i], A[i+8]}.
    for (int i = tid; i < 1152; i += 256) {
        int il = i - 8;
        float k0 = (il     >= 128 && il     <= 1151) ? stg[il - 128] : 0.0f;
        float k1 = (il - 1 >= 128 && il - 1 <= 1151) ? stg[il - 129] : 0.0f;
        float k2 = (il + 8 >= 128 && il + 8 <= 1151) ? stg[il - 120] : 0.0f;
        float k3 = (il + 7 >= 128 && il + 7 <= 1151) ? stg[il - 121] : 0.0f;
        float r0 = k0 - bf2f(bfbits(k0)), r1 = k1 - bf2f(bfbits(k1));
        float r2 = k2 - bf2f(bfbits(k2)), r3 = k3 - bf2f(bfbits(k3));
        uint2 hv = { packbf2(k0, k1), packbf2(k2, k3) };
        uint2 lv = { packbf2(r0, r1), packbf2(r2, r3) };
        A2H[i] = hv;
        A2L[i] = lv;
    }

    // ---- build u strip (16 rows) bf16 hi/lo ----
    for (int idx = tid; idx < NB * 256; idx += 256) {
        int n = idx >> 8, kq = idx & 255;
        int bg = bh * NB + n;
        float4 v = *(const float4*)(u + ((size_t)(bg * D_MODEL + d)) * LSEQ + kq * 4);
        float vv[4] = {v.x, v.y, v.z, v.w};
        uint16_t hb[4], lb[4];
        #pragma unroll
        for (int t = 0; t < 4; t++) {
            hb[t] = bfbits(vv[t]);
            lb[t] = bfbits(vv[t] - bf2f(hb[t]));
        }
        uint2 hv = { (uint32_t)hb[0] | ((uint32_t)hb[1] << 16),
                     (uint32_t)hb[2] | ((uint32_t)hb[3] << 16) };
        uint2 lv = { (uint32_t)lb[0] | ((uint32_t)lb[1] << 16),
                     (uint32_t)lb[2] | ((uint32_t)lb[3] << 16) };
        *(uint2*)(smem + OFF_UBH + n * PKB + kq * 8) = hv;
        *(uint2*)(smem + OFF_UBL + n * PKB + kq * 8) = lv;
    }
    __syncthreads();

    const int row = lane >> 2;
    const int kc  = (lane & 3) * 2;

    // ---- GEMM: kk outer (B cached), j inner unrolled w/ uniform guard ----
    float acc[8][2][4];
    #pragma unroll
    for (int j = 0; j < 8; j++)
        #pragma unroll
        for (int nt = 0; nt < 2; nt++)
            #pragma unroll
            for (int q = 0; q < 4; q++) acc[j][nt][q] = 0.0f;

    for (int kk = 0; kk < 64; kk++) {
        const int jlo = kk >> 3;
        // B fragments for this kk (reused across j)
        uint32_t bhv[2][2], blv[2][2];
        #pragma unroll
        for (int nt = 0; nt < 2; nt++) {
            const char* pb = smem + (nt * 8 + row) * PKB + (kk * 16 + kc) * 2;
            bhv[nt][0] = *(const uint32_t*)(pb + OFF_UBH);
            bhv[nt][1] = *(const uint32_t*)(pb + OFF_UBH + 16);
            blv[nt][0] = *(const uint32_t*)(pb + OFF_UBL);
            blv[nt][1] = *(const uint32_t*)(pb + OFF_UBL + 16);
        }
        // raw A2 index for j=0: ip = p+8, p = 128 + j*128 + w*16 + row - kc - 16*kk
        const int ip0 = 136 + w * 16 + row - kc - 16 * kk;
        #pragma unroll
        for (int j = 0; j < 8; j++) {
            if (j >= jlo) {
                const int ip = ip0 + j * 128;
                uint2 h01 = A2H[ip], h23 = A2H[ip - 8];
                uint2 l01 = A2L[ip], l23 = A2L[ip - 8];
                uint32_t ah[4] = {h01.x, h01.y, h23.x, h23.y};
                uint32_t al[4] = {l01.x, l01.y, l23.x, l23.y};
                #pragma unroll
                for (int nt = 0; nt < 2; nt++) {
                    mma16816(acc[j][nt], ah, bhv[nt]);
                    mma16816(acc[j][nt], ah, blv[nt]);
                    mma16816(acc[j][nt], al, bhv[nt]);
                }
            }
        }
    }

    // ---- epilogue: per j, stage 128(l) x 16(b) then skip + Cheb-GELU ----
    const float Dd = Dvec[d];
    const float cc5[5] = {1.371512430522f, -0.740775295685f, 0.134773988002f,
                          0.126019270103f, -0.239569101196f};
    for (int j = 0; j < 8; j++) {
        __syncthreads();
        #pragma unroll
        for (int nt = 0; nt < 2; nt++) {
            int bcol = nt * 8 + kc;
            int lml  = w * 16 + row;
            stg[bcol * 136 + lml]           = acc[j][nt][0];
            stg[(bcol + 1) * 136 + lml]     = acc[j][nt][1];
            stg[bcol * 136 + lml + 8]       = acc[j][nt][2];
            stg[(bcol + 1) * 136 + lml + 8] = acc[j][nt][3];
        }
        __syncthreads();

        const int bq  = tid >> 4;            // 0..15
        const int l4  = (tid & 15) * 4;      // 0..60
        const int bg  = bh * NB + bq;
        #pragma unroll
        for (int i = 0; i < 2; i++) {
            const int ll = l4 + i * 64;
            const int l  = j * 128 + ll;
            float4 y4 = *(const float4*)&stg[bq * 136 + ll];
            const size_t gofs = ((size_t)(bg * D_MODEL + d)) * LSEQ + l;
            float4 u4 = *(const float4*)(u + gofs);
            float yy[4] = {y4.x, y4.y, y4.z, y4.w};
            float uu[4] = {u4.x, u4.y, u4.z, u4.w};
            float rr[4];
            #pragma unroll
            for (int t = 0; t < 4; t++) {
                float x  = yy[t] + uu[t] * Dd;
                float tc = (2.0f * x - 10.0f) * 0.05f;
                float t0 = 1.0f, t1 = tc;
                float res = 6.04831644882f + 8.094460228971f * tc;
                #pragma unroll
                for (int q = 0; q < 5; q++) {
                    float ti = 2.0f * tc * t1 - t0;
                    res += cc5[q] * ti;
                    t0 = t1; t1 = ti;
                }
                rr[t] = res;
            }
            float4 r4 = {rr[0], rr[1], rr[2], rr[3]};
            *(float4*)(g_act + gofs) = r4;
        }
    }
}

// ---------------------------------------------------------------------------
// Kernel C (tensor): GLU GEMM + gate + Wdec-pool via mma.sync bf16 hi/lo.
// (unchanged from R12)
// ---------------------------------------------------------------------------
__global__ void __launch_bounds__(256) k_head(const float* __restrict__ b1,
                                              const float* __restrict__ Wdec,
                                              float* __restrict__ out)
{
    __shared__ uint32_t Bh[64 * 68];      // [l][d/2] hi pairs, pitch 68 u32
    __shared__ uint32_t Bl[64 * 68];
    __shared__ float red[256];

    const int tid  = threadIdx.x;
    const int w    = tid >> 5;
    const int lane = tid & 31;
    const int r    = lane >> 2;
    const int lc   = blockIdx.x;
    const int b    = blockIdx.y;

    const float* gsrc = g_act + (size_t)b * D_MODEL * LSEQ + lc * 64;
    for (int idx = tid; idx < 2048; idx += 256) {
        int dd = idx >> 4, l4 = (idx & 15) * 4;
        float4 v = *(const float4*)(gsrc + (size_t)dd * LSEQ + l4);
        float vv[4] = {v.x, v.y, v.z, v.w};
        #pragma unroll
        for (int t = 0; t < 4; t++) {
            uint16_t h = bfbits(vv[t]);
            uint16_t lo = bfbits(vv[t] - bf2f(h));
            ((uint16_t*)Bh)[(l4 + t) * 136 + dd] = h;
            ((uint16_t*)Bl)[(l4 + t) * 136 + dd] = lo;
        }
    }
    __syncthreads();

    const int oa0 = 16 * w + r, oa1 = oa0 + 8;
    float b1a0 = b1[oa0],        b1a1 = b1[oa1];
    float b1b0 = b1[oa0 + 128],  b1b1 = b1[oa1 + 128];
    float wd0  = Wdec[oa0],      wd1  = Wdec[oa1];

    float accA[2][4][4], accB[2][4][4];
    #pragma unroll
    for (int lh = 0; lh < 2; lh++)
        #pragma unroll
        for (int nt = 0; nt < 4; nt++)
            #pragma unroll
            for (int q = 0; q < 4; q++) { accA[lh][nt][q] = 0.0f; accB[lh][nt][q] = 0.0f; }

    #pragma unroll
    for (int ks = 0; ks < 8; ks++) {
        const int fidx0 = (((0 * 8 + w) * 8 + ks) * 32 + lane) * 4;
        const int fidx1 = (((1 * 8 + w) * 8 + ks) * 32 + lane) * 4;
        uint4 AH0 = *(const uint4*)&g_Wfh[fidx0];
        uint4 AL0 = *(const uint4*)&g_Wfl[fidx0];
        uint4 AH1 = *(const uint4*)&g_Wfh[fidx1];
        uint4 AL1 = *(const uint4*)&g_Wfl[fidx1];
        uint32_t ah0[4] = {AH0.x, AH0.y, AH0.z, AH0.w};
        uint32_t al0[4] = {AL0.x, AL0.y, AL0.z, AL0.w};
        uint32_t ah1[4] = {AH1.x, AH1.y, AH1.z, AH1.w};
        uint32_t al1[4] = {AL1.x, AL1.y, AL1.z, AL1.w};
        const int cu = ks * 8 + (lane & 3);

        #pragma unroll
        for (int lh = 0; lh < 2; lh++) {
            #pragma unroll
            for (int nt = 0; nt < 4; nt++) {
                const int lrow = lh * 32 + nt * 8 + r;
                uint32_t bhv[2] = { Bh[lrow * 68 + cu], Bh[lrow * 68 + cu + 4] };
                uint32_t blv[2] = { Bl[lrow * 68 + cu], Bl[lrow * 68 + cu + 4] };
                mma16816(accA[lh][nt], ah0, bhv);
                mma16816(accA[lh][nt], ah0, blv);
                mma16816(accA[lh][nt], al0, bhv);
                mma16816(accB[lh][nt], ah1, bhv);
                mma16816(accB[lh][nt], ah1, blv);
                mma16816(accB[lh][nt], al1, bhv);
            }
        }
    }

    float partial = 0.0f;
    #pragma unroll
    for (int lh = 0; lh < 2; lh++)
        #pragma unroll
        for (int nt = 0; nt < 4; nt++)
            #pragma unroll
            for (int cq = 0; cq < 4; cq++) {
                float ba  = (cq < 2) ? b1a0 : b1a1;
                float bb  = (cq < 2) ? b1b0 : b1b1;
                float wdv = (cq < 2) ? wd0  : wd1;
                float a    = accA[lh][nt][cq] + ba;
                float gv   = accB[lh][nt][cq] + bb;
                float gate = fminf(fmaxf(0.25f * gv + 0.5f, 0.0f), 1.0f);
                partial += wdv * (a * gate);
            }

    red[tid] = partial;
    __syncthreads();
    for (int s = 128; s > 0; s >>= 1) {
        if (tid < s) red[tid] += red[tid + s];
        __syncthreads();
    }
    if (tid == 0) atomicAdd(out + b, red[0] * (1.0f / 1024.0f));
}

__global__ void k_init(float* out, const float* __restrict__ bdec)
{
    int i = threadIdx.x;
    if (i < BATCH) out[i] = bdec[0];
}

// ---------------------------------------------------------------------------
extern "C" void kernel_launch(void* const* d_in, const int* in_sizes, int n_in,
                              void* d_out, int out_size)
{
    const float* u          = (const float*)d_in[0];
    const float* log_dt     = (const float*)d_in[1];
    const float* log_A_real = (const float*)d_in[2];
    const float* A_imag     = (const float*)d_in[3];
    const float* B_re       = (const float*)d_in[4];
    const float* B_im       = (const float*)d_in[5];
    const float* C_re       = (const float*)d_in[6];
    const float* C_im       = (const float*)d_in[7];
    const float* Dvec       = (const float*)d_in[8];
    const float* W1         = (const float*)d_in[9];
    const float* b1         = (const float*)d_in[10];
    const float* Wdec       = (const float*)d_in[11];
    const float* bdec       = (const float*)d_in[12];
    float* out = (float*)d_out;

    cudaFuncSetAttribute(k_conv, cudaFuncAttributeMaxDynamicSharedMemorySize, SMEM_CONV);

    k_init<<<1, 32>>>(out, bdec);
    k_prepW<<<16, 256>>>(W1);
    k_genK<<<dim3(D_MODEL, 4), 256>>>(log_dt, log_A_real, A_imag, B_re, B_im, C_re, C_im);
    k_conv<<<dim3(D_MODEL, 2), 256, SMEM_CONV>>>(u, Dvec);
    k_head<<<dim3(16, BATCH), 256>>>(b1, Wdec, out);
}

// round 16
// speedup vs baseline: 1.7030x; 1.7030x over previous
#include <cuda_runtime.h>
#include <cuda_bf16.h>
#include <math.h>
#include <stdint.h>

#define D_MODEL 128
#define D_STATE 64
#define LSEQ    1024
#define BATCH   32

// Scratch (static device globals: allocation-free per harness rules)
__device__ float g_K  [D_MODEL * LSEQ];                  // REVERSED kernel Krev[d][s] = K[d][1023-s]
__device__ float g_act[BATCH * D_MODEL * LSEQ];          // post-GELU activations
__device__ uint32_t g_Wfh[16384];                        // W1 hi, mma-fragment order
__device__ uint32_t g_Wfl[16384];                        // W1 lo, mma-fragment order

// ---------------------------------------------------------------------------
// helpers
// ---------------------------------------------------------------------------
__device__ __forceinline__ uint16_t bfbits(float x) {
    __nv_bfloat16 h = __float2bfloat16(x);
    return *(uint16_t*)&h;
}
__device__ __forceinline__ float bf2f(uint16_t b) {
    __nv_bfloat16 h = *(__nv_bfloat16*)&b;
    return __bfloat162float(h);
}
// mma.sync m16n8k16 row.col f32.bf16.bf16.f32 (sm_80+, no 'a' feature needed)
__device__ __forceinline__ void mma16816(float* c, const uint32_t* a, const uint32_t* b) {
    asm volatile(
        "mma.sync.aligned.m16n8k16.row.col.f32.bf16.bf16.f32 "
        "{%0,%1,%2,%3}, {%4,%5,%6,%7}, {%8,%9}, {%0,%1,%2,%3};"
        : "+f"(c[0]), "+f"(c[1]), "+f"(c[2]), "+f"(c[3])
        : "r"(a[0]), "r"(a[1]), "r"(a[2]), "r"(a[3]), "r"(b[0]), "r"(b[1]));
}

// fp32 Cody-Waite mod-2pi of an fp32 value (err <= ~7e-7 abs).
__device__ __forceinline__ float red2pi(float ph) {
    float n = rintf(ph * 0.15915494309189535f);
    float r = fmaf(n, -6.28125f, ph);
    return fmaf(n, -1.9353071795864769e-3f, r);
}

// ---------------------------------------------------------------------------
// Kernel A: K[d,m], stored REVERSED: g_K[d][1023-m] = K[d][m]
// ---------------------------------------------------------------------------
__global__ void k_genK(const float* __restrict__ log_dt,
                       const float* __restrict__ log_A_real,
                       const float* __restrict__ A_imag,
                       const float* __restrict__ B_re, const float* __restrict__ B_im,
                       const float* __restrict__ C_re, const float* __restrict__ C_im)
{
    const int d = blockIdx.x;
    __shared__ float arS[64], aiS[64], grS[64], giS[64];
    const int tid = threadIdx.x;

    if (tid < 64) {
        int n = tid;
        float dtv = expf(log_dt[d]);
        float Ar  = -expf(log_A_real[d * 64 + n]);
        float Ai  = A_imag[d * 64 + n];
        float ar  = Ar * dtv;
        float ai  = Ai * dtv;
        float r0  = red2pi(ai);
        float s, c;
        __sincosf(r0, &s, &c);
        float e   = expf(ar);
        float Abr = e * c, Abi = e * s;
        float nr = Abr - 1.0f, ni = Abi;
        float inv = 1.0f / (Ar * Ar + Ai * Ai);
        float br = (nr * Ar + ni * Ai) * inv;
        float bi = (ni * Ar - nr * Ai) * inv;
        float Br = B_re[d * 64 + n], Bi = B_im[d * 64 + n];
        float tr = br * Br - bi * Bi;
        float ti = br * Bi + bi * Br;
        float Cr = C_re[d * 64 + n], Ci = C_im[d * 64 + n];
        grS[n] = Cr * tr - Ci * ti;
        giS[n] = Cr * ti + Ci * tr;
        arS[n] = ar;
        aiS[n] = ai;
    }
    __syncthreads();

    const int l = blockIdx.y * 256 + tid;
    float lf = (float)l;
    float acc = 0.0f;
    #pragma unroll 4
    for (int n = 0; n < 64; n++) {
        float ph = aiS[n] * lf;
        float r  = red2pi(ph);
        float s, c;
        __sincosf(r, &s, &c);
        float e = __expf(arS[n] * lf);
        acc += e * (grS[n] * c - giS[n] * s);
    }
    g_K[d * LSEQ + (LSEQ - 1 - l)] = acc;      // reversed store
}

// ---------------------------------------------------------------------------
// W1 -> bf16 hi/lo in mma-fragment order (see k_head).
// ---------------------------------------------------------------------------
__global__ void k_prepW(const float* __restrict__ W1)
{
    int t = blockIdx.x * 256 + threadIdx.x;    // 0..4095
    int lane = t & 31;
    int ks = (t >> 5) & 7;
    int w  = (t >> 8) & 7;
    int h  = (t >> 11) & 1;
    int r  = lane >> 2;
    int cu = ks * 8 + (lane & 3);
    int oa0 = h * 128 + 16 * w + r, oa1 = oa0 + 8;
    int rowsel[4] = {oa0, oa1, oa0, oa1};
    int dsel[4]   = {2 * cu, 2 * cu, 2 * cu + 8, 2 * cu + 8};
    uint32_t hi[4], lo[4];
    #pragma unroll
    for (int i = 0; i < 4; i++) {
        float v0 = W1[rowsel[i] * 128 + dsel[i]];
        float v1 = W1[rowsel[i] * 128 + dsel[i] + 1];
        uint16_t h0 = bfbits(v0), h1 = bfbits(v1);
        uint16_t l0 = bfbits(v0 - bf2f(h0)), l1 = bfbits(v1 - bf2f(h1));
        hi[i] = (uint32_t)h0 | ((uint32_t)h1 << 16);
        lo[i] = (uint32_t)l0 | ((uint32_t)l1 << 16);
    }
    uint4 hv = {hi[0], hi[1], hi[2], hi[3]};
    uint4 lv = {lo[0], lo[1], lo[2], lo[3]};
    *(uint4*)&g_Wfh[(size_t)t * 4] = hv;
    *(uint4*)&g_Wfl[(size_t)t * 4] = lv;
}

// ---------------------------------------------------------------------------
// Kernel B: per-d Toeplitz conv via mma.sync bf16 hi/lo split (R12 structure,
// 52.7us proven) + SPLIT ACCUMULATORS: each of the 3 split terms (hh, hl, lh)
// gets its own accumulator set -> 12 independent HMMA dep-chains per j
// instead of 4 chains of length 3 (kernel was RAW-latency-bound).
// One CTA per d (grid 128), 256 threads = 8 warps.
// ---------------------------------------------------------------------------
#define PKB      2064                     // ub row pitch bytes (1032 bf16)
#define OFF_AH   0                        // 1160 u32 = 4640 B
#define OFF_AL   4640
#define OFF_STG  9280                     // 32*136 floats = 17408 B (also K scratch)
#define OFF_UBH  26688                    // 32 * 2064 = 66048 B
#define OFF_UBL  92736
#define SMEM_CONV 158784

__global__ void __launch_bounds__(256, 1) k_conv(const float* __restrict__ u,
                                                 const float* __restrict__ Dvec)
{
    extern __shared__ __align__(16) char smem[];
    uint32_t* AH  = (uint32_t*)(smem + OFF_AH);
    uint32_t* AL  = (uint32_t*)(smem + OFF_AL);
    float*    stg = (float*)(smem + OFF_STG);

    const int d    = blockIdx.x;
    const int tid  = threadIdx.x;
    const int w    = tid >> 5;
    const int lane = tid & 31;

    for (int i = tid; i < 1024; i += 256) stg[i] = g_K[d * LSEQ + i];
    __syncthreads();

    for (int i = tid; i < 1160; i += 256) {
        int il = i - 8;
        float k0 = (il  >= 128 && il  <= 1151) ? stg[il  - 128] : 0.0f;
        float k1 = (il-1 >= 128 && il-1 <= 1151) ? stg[il - 129] : 0.0f;
        uint16_t h0 = bfbits(k0), h1 = bfbits(k1);
        uint16_t l0 = bfbits(k0 - bf2f(h0)), l1 = bfbits(k1 - bf2f(h1));
        AH[i] = (uint32_t)h0 | ((uint32_t)h1 << 16);
        AL[i] = (uint32_t)l0 | ((uint32_t)l1 << 16);
    }

    for (int idx = tid; idx < 8192; idx += 256) {
        int n = idx >> 8, kq = idx & 255;
        float4 v = *(const float4*)(u + ((size_t)(n * D_MODEL + d)) * LSEQ + kq * 4);
        float vv[4] = {v.x, v.y, v.z, v.w};
        uint16_t hb[4], lb[4];
        #pragma unroll
        for (int t = 0; t < 4; t++) {
            hb[t] = bfbits(vv[t]);
            lb[t] = bfbits(vv[t] - bf2f(hb[t]));
        }
        uint2 hv = { (uint32_t)hb[0] | ((uint32_t)hb[1] << 16),
                     (uint32_t)hb[2] | ((uint32_t)hb[3] << 16) };
        uint2 lv = { (uint32_t)lb[0] | ((uint32_t)lb[1] << 16),
                     (uint32_t)lb[2] | ((uint32_t)lb[3] << 16) };
        *(uint2*)(smem + OFF_UBH + n * PKB + kq * 8) = hv;
        *(uint2*)(smem + OFF_UBL + n * PKB + kq * 8) = lv;
    }
    __syncthreads();

    const uint32_t* AHl = AH + 8;
    const uint32_t* ALl = AL + 8;
    const int row  = lane >> 2;
    const int kc   = (lane & 3) * 2;
    const float Dd = Dvec[d];
    const float cc5[5] = {1.371512430522f, -0.740775295685f, 0.134773988002f,
                          0.126019270103f, -0.239569101196f};

    for (int j = 0; j < 8; j++) {
        // 3 independent accumulator sets: [term][nt][quad]
        float acc0[4][4], acc1[4][4], acc2[4][4];
        #pragma unroll
        for (int a = 0; a < 4; a++)
            #pragma unroll
            for (int b = 0; b < 4; b++) {
                acc0[a][b] = 0.0f; acc1[a][b] = 0.0f; acc2[a][b] = 0.0f;
            }

        const int nk = 8 * (j + 1);
        const int Pw = 128 + j * 128 + w * 16 + row - kc;

        for (int kk = 0; kk < nk; kk++) {
            const int k0 = kk * 16;
            const int p  = Pw - k0;
            uint32_t ah[4], al[4];
            ah[0] = AHl[p]; ah[1] = AHl[p + 8]; ah[2] = AHl[p - 8]; ah[3] = ah[0];
            al[0] = ALl[p]; al[1] = ALl[p + 8]; al[2] = ALl[p - 8]; al[3] = al[0];
            const int bofs = (k0 + kc) * 2;
            #pragma unroll
            for (int nt = 0; nt < 4; nt++) {
                const char* pb = smem + (nt * 8 + row) * PKB + bofs;
                uint32_t bh[2] = { *(const uint32_t*)(pb + OFF_UBH),
                                   *(const uint32_t*)(pb + OFF_UBH + 16) };
                uint32_t bl[2] = { *(const uint32_t*)(pb + OFF_UBL),
                                   *(const uint32_t*)(pb + OFF_UBL + 16) };
                mma16816(acc0[nt], ah, bh);      // hh
                mma16816(acc1[nt], ah, bl);      // hl
                mma16816(acc2[nt], al, bh);      // lh
            }
        }

        // ---- stage this 128(l) x 32(b) chunk (terms merged): stg[b][l] ----
        #pragma unroll
        for (int nt = 0; nt < 4; nt++) {
            int bcol = nt * 8 + kc;
            int lml  = w * 16 + row;
            stg[bcol * 136 + lml]           = acc0[nt][0] + acc1[nt][0] + acc2[nt][0];
            stg[(bcol + 1) * 136 + lml]     = acc0[nt][1] + acc1[nt][1] + acc2[nt][1];
            stg[bcol * 136 + lml + 8]       = acc0[nt][2] + acc1[nt][2] + acc2[nt][2];
            stg[(bcol + 1) * 136 + lml + 8] = acc0[nt][3] + acc1[nt][3] + acc2[nt][3];
        }
        __syncthreads();

        // ---- coalesced epilogue: skip + Cheb-GELU -> g_act ----
        {
            const int bq  = tid >> 3;            // 0..31
            const int l4  = (tid & 7) * 4;       // 0..28
            #pragma unroll
            for (int i = 0; i < 4; i++) {
                const int ll = l4 + i * 32;
                const int l  = j * 128 + ll;
                float4 y4 = *(const float4*)&stg[bq * 136 + ll];
                const size_t gofs = ((size_t)(bq * D_MODEL + d)) * LSEQ + l;
                float4 u4 = *(const float4*)(u + gofs);
                float yy[4] = {y4.x, y4.y, y4.z, y4.w};
                float uu[4] = {u4.x, u4.y, u4.z, u4.w};
                float rr[4];
                #pragma unroll
                for (int t = 0; t < 4; t++) {
                    float x  = yy[t] + uu[t] * Dd;
                    float tc = (2.0f * x - 10.0f) * 0.05f;
                    float t0 = 1.0f, t1 = tc;
                    float res = 6.04831644882f + 8.094460228971f * tc;
                    #pragma unroll
                    for (int q = 0; q < 5; q++) {
                        float ti = 2.0f * tc * t1 - t0;
                        res += cc5[q] * ti;
                        t0 = t1; t1 = ti;
                    }
                    rr[t] = res;
                }
                float4 r4 = {rr[0], rr[1], rr[2], rr[3]};
                *(float4*)(g_act + gofs) = r4;
            }
        }
        __syncthreads();
    }
}

// ---------------------------------------------------------------------------
// Kernel C (tensor): GLU GEMM + gate + Wdec-pool via mma.sync bf16 hi/lo.
// (unchanged from R12)
// ---------------------------------------------------------------------------
__global__ void __launch_bounds__(256) k_head(const float* __restrict__ b1,
                                              const float* __restrict__ Wdec,
                                              float* __restrict__ out)
{
    __shared__ uint32_t Bh[64 * 68];      // [l][d/2] hi pairs, pitch 68 u32
    __shared__ uint32_t Bl[64 * 68];
    __shared__ float red[256];

    const int tid  = threadIdx.x;
    const int w    = tid >> 5;
    const int lane = tid & 31;
    const int r    = lane >> 2;
    const int lc   = blockIdx.x;
    const int b    = blockIdx.y;

    const float* gsrc = g_act + (size_t)b * D_MODEL * LSEQ + lc * 64;
    for (int idx = tid; idx < 2048; idx += 256) {
        int dd = idx >> 4, l4 = (idx & 15) * 4;
        float4 v = *(const float4*)(gsrc + (size_t)dd * LSEQ + l4);
        float vv[4] = {v.x, v.y, v.z, v.w};
        #pragma unroll
        for (int t = 0; t < 4; t++) {
            uint16_t h = bfbits(vv[t]);
            uint16_t lo = bfbits(vv[t] - bf2f(h));
            ((uint16_t*)Bh)[(l4 + t) * 136 + dd] = h;
            ((uint16_t*)Bl)[(l4 + t) * 136 + dd] = lo;
        }
    }
    __syncthreads();

    const int oa0 = 16 * w + r, oa1 = oa0 + 8;
    float b1a0 = b1[oa0],        b1a1 = b1[oa1];
    float b1b0 = b1[oa0 + 128],  b1b1 = b1[oa1 + 128];
    float wd0  = Wdec[oa0],      wd1  = Wdec[oa1];

    float accA[2][4][4], accB[2][4][4];
    #pragma unroll
    for (int lh = 0; lh < 2; lh++)
        #pragma unroll
        for (int nt = 0; nt < 4; nt++)
            #pragma unroll
            for (int q = 0; q < 4; q++) { accA[lh][nt][q] = 0.0f; accB[lh][nt][q] = 0.0f; }

    #pragma unroll
    for (int ks = 0; ks < 8; ks++) {
        const int fidx0 = (((0 * 8 + w) * 8 + ks) * 32 + lane) * 4;
        const int fidx1 = (((1 * 8 + w) * 8 + ks) * 32 + lane) * 4;
        uint4 AH0 = *(const uint4*)&g_Wfh[fidx0];
        uint4 AL0 = *(const uint4*)&g_Wfl[fidx0];
        uint4 AH1 = *(const uint4*)&g_Wfh[fidx1];
        uint4 AL1 = *(const uint4*)&g_Wfl[fidx1];
        uint32_t ah0[4] = {AH0.x, AH0.y, AH0.z, AH0.w};
        uint32_t al0[4] = {AL0.x, AL0.y, AL0.z, AL0.w};
        uint32_t ah1[4] = {AH1.x, AH1.y, AH1.z, AH1.w};
        uint32_t al1[4] = {AL1.x, AL1.y, AL1.z, AL1.w};
        const int cu = ks * 8 + (lane & 3);

        #pragma unroll
        for (int lh = 0; lh < 2; lh++) {
            #pragma unroll
            for (int nt = 0; nt < 4; nt++) {
                const int lrow = lh * 32 + nt * 8 + r;
                uint32_t bhv[2] = { Bh[lrow * 68 + cu], Bh[lrow * 68 + cu + 4] };
                uint32_t blv[2] = { Bl[lrow * 68 + cu], Bl[lrow * 68 + cu + 4] };
                mma16816(accA[lh][nt], ah0, bhv);
                mma16816(accA[lh][nt], ah0, blv);
                mma16816(accA[lh][nt], al0, bhv);
                mma16816(accB[lh][nt], ah1, bhv);
                mma16816(accB[lh][nt], ah1, blv);
                mma16816(accB[lh][nt], al1, bhv);
            }
        }
    }

    float partial = 0.0f;
    #pragma unroll
    for (int lh = 0; lh < 2; lh++)
        #pragma unroll
        for (int nt = 0; nt < 4; nt++)
            #pragma unroll
            for (int cq = 0; cq < 4; cq++) {
                float ba  = (cq < 2) ? b1a0 : b1a1;
                float bb  = (cq < 2) ? b1b0 : b1b1;
                float wdv = (cq < 2) ? wd0  : wd1;
                float a    = accA[lh][nt][cq] + ba;
                float gv   = accB[lh][nt][cq] + bb;
                float gate = fminf(fmaxf(0.25f * gv + 0.5f, 0.0f), 1.0f);
                partial += wdv * (a * gate);
            }

    red[tid] = partial;
    __syncthreads();
    for (int s = 128; s > 0; s >>= 1) {
        if (tid < s) red[tid] += red[tid + s];
        __syncthreads();
    }
    if (tid == 0) atomicAdd(out + b, red[0] * (1.0f / 1024.0f));
}

__global__ void k_init(float* out, const float* __restrict__ bdec)
{
    int i = threadIdx.x;
    if (i < BATCH) out[i] = bdec[0];
}

// ---------------------------------------------------------------------------
extern "C" void kernel_launch(void* const* d_in, const int* in_sizes, int n_in,
                              void* d_out, int out_size)
{
    const float* u          = (const float*)d_in[0];
    const float* log_dt     = (const float*)d_in[1];
    const float* log_A_real = (const float*)d_in[2];
    const float* A_imag     = (const float*)d_in[3];
    const float* B_re       = (const float*)d_in[4];
    const float* B_im       = (const float*)d_in[5];
    const float* C_re       = (const float*)d_in[6];
    const float* C_im       = (const float*)d_in[7];
    const float* Dvec       = (const float*)d_in[8];
    const float* W1         = (const float*)d_in[9];
    const float* b1         = (const float*)d_in[10];
    const float* Wdec       = (const float*)d_in[11];
    const float* bdec       = (const float*)d_in[12];
    float* out = (float*)d_out;

    cudaFuncSetAttribute(k_conv, cudaFuncAttributeMaxDynamicSharedMemorySize, SMEM_CONV);

    k_init<<<1, 32>>>(out, bdec);
    k_prepW<<<16, 256>>>(W1);
    k_genK<<<dim3(D_MODEL, 4), 256>>>(log_dt, log_A_real, A_imag, B_re, B_im, C_re, C_im);
    k_conv<<<D_MODEL, 256, SMEM_CONV>>>(u, Dvec);
    k_head<<<dim3(16, BATCH), 256>>>(b1, Wdec, out);
}

// round 17
// speedup vs baseline: 1.7036x; 1.0004x over previous
#include <cuda_runtime.h>
#include <cuda_bf16.h>
#include <math.h>
#include <stdint.h>

#define D_MODEL 128
#define D_STATE 64
#define LSEQ    1024
#define BATCH   32

// Scratch (static device globals: allocation-free per harness rules)
__device__ float g_K  [D_MODEL * LSEQ];                  // REVERSED kernel Krev[d][s] = K[d][1023-s]
__device__ float g_act[BATCH * D_MODEL * LSEQ];          // post-GELU activations
__device__ uint32_t g_Wfh[16384];                        // W1 hi, mma-fragment order
__device__ uint32_t g_Wfl[16384];                        // W1 lo, mma-fragment order

// ---------------------------------------------------------------------------
// helpers
// ---------------------------------------------------------------------------
__device__ __forceinline__ uint16_t bfbits(float x) {
    __nv_bfloat16 h = __float2bfloat16(x);
    return *(uint16_t*)&h;
}
__device__ __forceinline__ float bf2f(uint16_t b) {
    __nv_bfloat16 h = *(__nv_bfloat16*)&b;
    return __bfloat162float(h);
}
// mma.sync m16n8k16 row.col f32.bf16.bf16.f32 (sm_80+, no 'a' feature needed)
__device__ __forceinline__ void mma16816(float* c, const uint32_t* a, const uint32_t* b) {
    asm volatile(
        "mma.sync.aligned.m16n8k16.row.col.f32.bf16.bf16.f32 "
        "{%0,%1,%2,%3}, {%4,%5,%6,%7}, {%8,%9}, {%0,%1,%2,%3};"
        : "+f"(c[0]), "+f"(c[1]), "+f"(c[2]), "+f"(c[3])
        : "r"(a[0]), "r"(a[1]), "r"(a[2]), "r"(a[3]), "r"(b[0]), "r"(b[1]));
}

// fp32 Cody-Waite mod-2pi of an fp32 value (err <= ~7e-7 abs).
__device__ __forceinline__ float red2pi(float ph) {
    float n = rintf(ph * 0.15915494309189535f);
    float r = fmaf(n, -6.28125f, ph);
    return fmaf(n, -1.9353071795864769e-3f, r);
}

// ---------------------------------------------------------------------------
// Kernel A: K[d,m], stored REVERSED: g_K[d][1023-m] = K[d][m]
// Also absorbs W1 fragment pre-split (blocks y==0, x<16) and out-init
// (block y==0, x==16) to save two kernel launches.
// ---------------------------------------------------------------------------
__global__ void k_genK(const float* __restrict__ log_dt,
                       const float* __restrict__ log_A_real,
                       const float* __restrict__ A_imag,
                       const float* __restrict__ B_re, const float* __restrict__ B_im,
                       const float* __restrict__ C_re, const float* __restrict__ C_im,
                       const float* __restrict__ W1,
                       const float* __restrict__ bdec,
                       float* __restrict__ out)
{
    const int d = blockIdx.x;
    __shared__ float arS[64], aiS[64], grS[64], giS[64];
    const int tid = threadIdx.x;

    if (tid < 64) {
        int n = tid;
        float dtv = expf(log_dt[d]);
        float Ar  = -expf(log_A_real[d * 64 + n]);
        float Ai  = A_imag[d * 64 + n];
        float ar  = Ar * dtv;
        float ai  = Ai * dtv;
        float r0  = red2pi(ai);
        float s, c;
        __sincosf(r0, &s, &c);
        float e   = expf(ar);
        float Abr = e * c, Abi = e * s;
        float nr = Abr - 1.0f, ni = Abi;
        float inv = 1.0f / (Ar * Ar + Ai * Ai);
        float br = (nr * Ar + ni * Ai) * inv;
        float bi = (ni * Ar - nr * Ai) * inv;
        float Br = B_re[d * 64 + n], Bi = B_im[d * 64 + n];
        float tr = br * Br - bi * Bi;
        float ti = br * Bi + bi * Br;
        float Cr = C_re[d * 64 + n], Ci = C_im[d * 64 + n];
        grS[n] = Cr * tr - Ci * ti;
        giS[n] = Cr * ti + Ci * tr;
        arS[n] = ar;
        aiS[n] = ai;
    }
    __syncthreads();

    const int l = blockIdx.y * 256 + tid;
    float lf = (float)l;
    float acc = 0.0f;
    #pragma unroll 4
    for (int n = 0; n < 64; n++) {
        float ph = aiS[n] * lf;
        float r  = red2pi(ph);
        float s, c;
        __sincosf(r, &s, &c);
        float e = __expf(arS[n] * lf);
        acc += e * (grS[n] * c - giS[n] * s);
    }
    g_K[d * LSEQ + (LSEQ - 1 - l)] = acc;      // reversed store

    // ---- absorbed: W1 fragment pre-split + out init ----
    if (blockIdx.y == 0) {
        if (blockIdx.x < 16) {
            int t = blockIdx.x * 256 + tid;    // 0..4095
            int lane = t & 31;
            int ks = (t >> 5) & 7;
            int w  = (t >> 8) & 7;
            int h  = (t >> 11) & 1;
            int r  = lane >> 2;
            int cu = ks * 8 + (lane & 3);
            int oa0 = h * 128 + 16 * w + r, oa1 = oa0 + 8;
            int rowsel[4] = {oa0, oa1, oa0, oa1};
            int dsel[4]   = {2 * cu, 2 * cu, 2 * cu + 8, 2 * cu + 8};
            uint32_t hi[4], lo[4];
            #pragma unroll
            for (int i = 0; i < 4; i++) {
                float v0 = W1[rowsel[i] * 128 + dsel[i]];
                float v1 = W1[rowsel[i] * 128 + dsel[i] + 1];
                uint16_t h0 = bfbits(v0), h1 = bfbits(v1);
                uint16_t l0 = bfbits(v0 - bf2f(h0)), l1 = bfbits(v1 - bf2f(h1));
                hi[i] = (uint32_t)h0 | ((uint32_t)h1 << 16);
                lo[i] = (uint32_t)l0 | ((uint32_t)l1 << 16);
            }
            uint4 hv = {hi[0], hi[1], hi[2], hi[3]};
            uint4 lv = {lo[0], lo[1], lo[2], lo[3]};
            *(uint4*)&g_Wfh[(size_t)t * 4] = hv;
            *(uint4*)&g_Wfl[(size_t)t * 4] = lv;
        }
        if (blockIdx.x == 16 && tid < BATCH) out[tid] = bdec[0];
    }
}

// ---------------------------------------------------------------------------
// Kernel B: per-d Toeplitz conv via mma.sync bf16 hi/lo split.
// R16 structure + DOUBLE-BUFFERED epilogue staging (one sync per j; the j
// epilogue interleaves with j+1's MMA phase) + u read from smem (bf16 hi+lo
// reconstruction) instead of gmem.
// One CTA per d (grid 128), 256 threads = 8 warps.
// ---------------------------------------------------------------------------
#define PKB      2064                     // ub row pitch bytes (1032 bf16)
#define OFF_AH   0                        // 1160 u32 = 4640 B
#define OFF_AL   4640
#define OFF_STG0 9280                     // 32*136 floats = 17408 B (also K scratch)
#define OFF_STG1 26688                    // second staging buffer
#define OFF_UBH  44096                    // 32 * 2064 = 66048 B
#define OFF_UBL  110144
#define SMEM_CONV 176192

__global__ void __launch_bounds__(256, 1) k_conv(const float* __restrict__ u,
                                                 const float* __restrict__ Dvec)
{
    extern __shared__ __align__(16) char smem[];
    uint32_t* AH  = (uint32_t*)(smem + OFF_AH);
    uint32_t* AL  = (uint32_t*)(smem + OFF_AL);
    float*    stgK = (float*)(smem + OFF_STG0);   // K scratch during build

    const int d    = blockIdx.x;
    const int tid  = threadIdx.x;
    const int w    = tid >> 5;
    const int lane = tid & 31;

    for (int i = tid; i < 1024; i += 256) stgK[i] = g_K[d * LSEQ + i];
    __syncthreads();

    for (int i = tid; i < 1160; i += 256) {
        int il = i - 8;
        float k0 = (il  >= 128 && il  <= 1151) ? stgK[il  - 128] : 0.0f;
        float k1 = (il-1 >= 128 && il-1 <= 1151) ? stgK[il - 129] : 0.0f;
        uint16_t h0 = bfbits(k0), h1 = bfbits(k1);
        uint16_t l0 = bfbits(k0 - bf2f(h0)), l1 = bfbits(k1 - bf2f(h1));
        AH[i] = (uint32_t)h0 | ((uint32_t)h1 << 16);
        AL[i] = (uint32_t)l0 | ((uint32_t)l1 << 16);
    }

    for (int idx = tid; idx < 8192; idx += 256) {
        int n = idx >> 8, kq = idx & 255;
        float4 v = *(const float4*)(u + ((size_t)(n * D_MODEL + d)) * LSEQ + kq * 4);
        float vv[4] = {v.x, v.y, v.z, v.w};
        uint16_t hb[4], lb[4];
        #pragma unroll
        for (int t = 0; t < 4; t++) {
            hb[t] = bfbits(vv[t]);
            lb[t] = bfbits(vv[t] - bf2f(hb[t]));
        }
        uint2 hv = { (uint32_t)hb[0] | ((uint32_t)hb[1] << 16),
                     (uint32_t)hb[2] | ((uint32_t)hb[3] << 16) };
        uint2 lv = { (uint32_t)lb[0] | ((uint32_t)lb[1] << 16),
                     (uint32_t)lb[2] | ((uint32_t)lb[3] << 16) };
        *(uint2*)(smem + OFF_UBH + n * PKB + kq * 8) = hv;
        *(uint2*)(smem + OFF_UBL + n * PKB + kq * 8) = lv;
    }
    __syncthreads();   // A/ub ready; K-scratch reads done (stg0 reusable)

    const uint32_t* AHl = AH + 8;
    const uint32_t* ALl = AL + 8;
    const int row  = lane >> 2;
    const int kc   = (lane & 3) * 2;
    const float Dd = Dvec[d];
    const float cc5[5] = {1.371512430522f, -0.740775295685f, 0.134773988002f,
                          0.126019270103f, -0.239569101196f};

    for (int j = 0; j < 8; j++) {
        float* stg = (float*)(smem + ((j & 1) ? OFF_STG1 : OFF_STG0));

        // 3 independent accumulator sets: hh, hl, lh
        float acc0[4][4], acc1[4][4], acc2[4][4];
        #pragma unroll
        for (int a = 0; a < 4; a++)
            #pragma unroll
            for (int b = 0; b < 4; b++) {
                acc0[a][b] = 0.0f; acc1[a][b] = 0.0f; acc2[a][b] = 0.0f;
            }

        const int nk = 8 * (j + 1);
        const int Pw = 128 + j * 128 + w * 16 + row - kc;

        for (int kk = 0; kk < nk; kk++) {
            const int k0 = kk * 16;
            const int p  = Pw - k0;
            uint32_t ah[4], al[4];
            ah[0] = AHl[p]; ah[1] = AHl[p + 8]; ah[2] = AHl[p - 8]; ah[3] = ah[0];
            al[0] = ALl[p]; al[1] = ALl[p + 8]; al[2] = ALl[p - 8]; al[3] = al[0];
            const int bofs = (k0 + kc) * 2;
            #pragma unroll
            for (int nt = 0; nt < 4; nt++) {
                const char* pb = smem + (nt * 8 + row) * PKB + bofs;
                uint32_t bh[2] = { *(const uint32_t*)(pb + OFF_UBH),
                                   *(const uint32_t*)(pb + OFF_UBH + 16) };
                uint32_t bl[2] = { *(const uint32_t*)(pb + OFF_UBL),
                                   *(const uint32_t*)(pb + OFF_UBL + 16) };
                mma16816(acc0[nt], ah, bh);      // hh
                mma16816(acc1[nt], ah, bl);      // hl
                mma16816(acc2[nt], al, bh);      // lh
            }
        }

        // ---- stage this 128(l) x 32(b) chunk (terms merged): stg[b][l] ----
        #pragma unroll
        for (int nt = 0; nt < 4; nt++) {
            int bcol = nt * 8 + kc;
            int lml  = w * 16 + row;
            stg[bcol * 136 + lml]           = acc0[nt][0] + acc1[nt][0] + acc2[nt][0];
            stg[(bcol + 1) * 136 + lml]     = acc0[nt][1] + acc1[nt][1] + acc2[nt][1];
            stg[bcol * 136 + lml + 8]       = acc0[nt][2] + acc1[nt][2] + acc2[nt][2];
            stg[(bcol + 1) * 136 + lml + 8] = acc0[nt][3] + acc1[nt][3] + acc2[nt][3];
        }
        __syncthreads();   // single barrier per j (double-buffered staging)

        // ---- epilogue: skip (u from smem) + Cheb-GELU -> g_act ----
        // Interleaves with next j's MMA phase in the instruction stream.
        {
            const int bq  = tid >> 3;            // 0..31
            const int l4  = (tid & 7) * 4;       // 0..28
            #pragma unroll
            for (int i = 0; i < 4; i++) {
                const int ll = l4 + i * 32;
                const int l  = j * 128 + ll;
                float4 y4 = *(const float4*)&stg[bq * 136 + ll];
                uint2 hvu = *(const uint2*)(smem + OFF_UBH + bq * PKB + l * 2);
                uint2 lvu = *(const uint2*)(smem + OFF_UBL + bq * PKB + l * 2);
                float uu[4] = {
                    bf2f((uint16_t)(hvu.x & 0xffff)) + bf2f((uint16_t)(lvu.x & 0xffff)),
                    bf2f((uint16_t)(hvu.x >> 16))    + bf2f((uint16_t)(lvu.x >> 16)),
                    bf2f((uint16_t)(hvu.y & 0xffff)) + bf2f((uint16_t)(lvu.y & 0xffff)),
                    bf2f((uint16_t)(hvu.y >> 16))    + bf2f((uint16_t)(lvu.y >> 16)) };
                float yy[4] = {y4.x, y4.y, y4.z, y4.w};
                float rr[4];
                #pragma unroll
                for (int t = 0; t < 4; t++) {
                    float x  = yy[t] + uu[t] * Dd;
                    float tc = (2.0f * x - 10.0f) * 0.05f;
                    float t0 = 1.0f, t1 = tc;
                    float res = 6.04831644882f + 8.094460228971f * tc;
                    #pragma unroll
                    for (int q = 0; q < 5; q++) {
                        float ti = 2.0f * tc * t1 - t0;
                        res += cc5[q] * ti;
                        t0 = t1; t1 = ti;
                    }
                    rr[t] = res;
                }
                float4 r4 = {rr[0], rr[1], rr[2], rr[3]};
                *(float4*)(g_act + ((size_t)(bq * D_MODEL + d)) * LSEQ + l) = r4;
            }
        }
        // no second sync: buf[j&1] next written at stage(j+2), after sync(j+1)
    }
}

// ---------------------------------------------------------------------------
// Kernel C (tensor): GLU GEMM + gate + Wdec-pool via mma.sync bf16 hi/lo.
// (unchanged from R12)
// ---------------------------------------------------------------------------
__global__ void __launch_bounds__(256) k_head(const float* __restrict__ b1,
                                              const float* __restrict__ Wdec,
                                              float* __restrict__ out)
{
    __shared__ uint32_t Bh[64 * 68];      // [l][d/2] hi pairs, pitch 68 u32
    __shared__ uint32_t Bl[64 * 68];
    __shared__ float red[256];

    const int tid  = threadIdx.x;
    const int w    = tid >> 5;
    const int lane = tid & 31;
    const int r    = lane >> 2;
    const int lc   = blockIdx.x;
    const int b    = blockIdx.y;

    const float* gsrc = g_act + (size_t)b * D_MODEL * LSEQ + lc * 64;
    for (int idx = tid; idx < 2048; idx += 256) {
        int dd = idx >> 4, l4 = (idx & 15) * 4;
        float4 v = *(const float4*)(gsrc + (size_t)dd * LSEQ + l4);
        float vv[4] = {v.x, v.y, v.z, v.w};
        #pragma unroll
        for (int t = 0; t < 4; t++) {
            uint16_t h = bfbits(vv[t]);
            uint16_t lo = bfbits(vv[t] - bf2f(h));
            ((uint16_t*)Bh)[(l4 + t) * 136 + dd] = h;
            ((uint16_t*)Bl)[(l4 + t) * 136 + dd] = lo;
        }
    }
    __syncthreads();

    const int oa0 = 16 * w + r, oa1 = oa0 + 8;
    float b1a0 = b1[oa0],        b1a1 = b1[oa1];
    float b1b0 = b1[oa0 + 128],  b1b1 = b1[oa1 + 128];
    float wd0  = Wdec[oa0],      wd1  = Wdec[oa1];

    float accA[2][4][4], accB[2][4][4];
    #pragma unroll
    for (int lh = 0; lh < 2; lh++)
        #pragma unroll
        for (int nt = 0; nt < 4; nt++)
            #pragma unroll
            for (int q = 0; q < 4; q++) { accA[lh][nt][q] = 0.0f; accB[lh][nt][q] = 0.0f; }

    #pragma unroll
    for (int ks = 0; ks < 8; ks++) {
        const int fidx0 = (((0 * 8 + w) * 8 + ks) * 32 + lane) * 4;
        const int fidx1 = (((1 * 8 + w) * 8 + ks) * 32 + lane) * 4;
        uint4 AH0 = *(const uint4*)&g_Wfh[fidx0];
        uint4 AL0 = *(const uint4*)&g_Wfl[fidx0];
        uint4 AH1 = *(const uint4*)&g_Wfh[fidx1];
        uint4 AL1 = *(const uint4*)&g_Wfl[fidx1];
        uint32_t ah0[4] = {AH0.x, AH0.y, AH0.z, AH0.w};
        uint32_t al0[4] = {AL0.x, AL0.y, AL0.z, AL0.w};
        uint32_t ah1[4] = {AH1.x, AH1.y, AH1.z, AH1.w};
        uint32_t al1[4] = {AL1.x, AL1.y, AL1.z, AL1.w};
        const int cu = ks * 8 + (lane & 3);

        #pragma unroll
        for (int lh = 0; lh < 2; lh++) {
            #pragma unroll
            for (int nt = 0; nt < 4; nt++) {
                const int lrow = lh * 32 + nt * 8 + r;
                uint32_t bhv[2] = { Bh[lrow * 68 + cu], Bh[lrow * 68 + cu + 4] };
                uint32_t blv[2] = { Bl[lrow * 68 + cu], Bl[lrow * 68 + cu + 4] };
                mma16816(accA[lh][nt], ah0, bhv);
                mma16816(accA[lh][nt], ah0, blv);
                mma16816(accA[lh][nt], al0, bhv);
                mma16816(accB[lh][nt], ah1, bhv);
                mma16816(accB[lh][nt], ah1, blv);
                mma16816(accB[lh][nt], al1, bhv);
            }
        }
    }

    float partial = 0.0f;
    #pragma unroll
    for (int lh = 0; lh < 2; lh++)
        #pragma unroll
        for (int nt = 0; nt < 4; nt++)
            #pragma unroll
            for (int cq = 0; cq < 4; cq++) {
                float ba  = (cq < 2) ? b1a0 : b1a1;
                float bb  = (cq < 2) ? b1b0 : b1b1;
                float wdv = (cq < 2) ? wd0  : wd1;
                float a    = accA[lh][nt][cq] + ba;
                float gv   = accB[lh][nt][cq] + bb;
                float gate = fminf(fmaxf(0.25f * gv + 0.5f, 0.0f), 1.0f);
                partial += wdv * (a * gate);
            }

    red[tid] = partial;
    __syncthreads();
    for (int s = 128; s > 0; s >>= 1) {
        if (tid < s) red[tid] += red[tid + s];
        __syncthreads();
    }
    if (tid == 0) atomicAdd(out + b, red[0] * (1.0f / 1024.0f));
}

// ---------------------------------------------------------------------------
extern "C" void kernel_launch(void* const* d_in, const int* in_sizes, int n_in,
                              void* d_out, int out_size)
{
    const float* u          = (const float*)d_in[0];
    const float* log_dt     = (const float*)d_in[1];
    const float* log_A_real = (const float*)d_in[2];
    const float* A_imag     = (const float*)d_in[3];
    const float* B_re       = (const float*)d_in[4];
    const float* B_im       = (const float*)d_in[5];
    const float* C_re       = (const float*)d_in[6];
    const float* C_im       = (const float*)d_in[7];
    const float* Dvec       = (const float*)d_in[8];
    const float* W1         = (const float*)d_in[9];
    const float* b1         = (const float*)d_in[10];
    const float* Wdec       = (const float*)d_in[11];
    const float* bdec       = (const float*)d_in[12];
    float* out = (float*)d_out;

    cudaFuncSetAttribute(k_conv, cudaFuncAttributeMaxDynamicSharedMemorySize, SMEM_CONV);

    k_genK<<<dim3(D_MODEL, 4), 256>>>(log_dt, log_A_real, A_imag,
                                      B_re, B_im, C_re, C_im, W1, bdec, out);
    k_conv<<<D_MODEL, 256, SMEM_CONV>>>(u, Dvec);
    k_head<<<dim3(16, BATCH), 256>>>(b1, Wdec, out);
}